// round 10
// baseline (speedup 1.0000x reference)
#include <cuda_runtime.h>
#include <cstdint>

#define MM   6
#define BB   128
#define TT   32
#define DINN 64
#define HHH  512
#define EEE  512
#define NEMB 32

#define MAXC      80
#define ROWS      64     // token rows per block: 2 batches x 32
#define XS_STRIDE 72     // words; mod 32 = 8 -> conflict-free LDS.64 A-fragments
#define HS_STRIDE 520    // words; mod 32 = 8

// weight ring: per-warp, 3 stages x (8 rows x 160B)
#define WROW_B   160
#define WSTG_B   (8 * WROW_B)       // 1280
#define WRING_B  (3 * WSTG_B)       // 3840
#define XS_BYTES (ROWS * XS_STRIDE * 4)              // 18432
#define HS_BYTES (ROWS * HS_STRIDE * 4)              // 133120
#define WR_OFF_B (XS_BYTES + HS_BYTES)               // 151552
#define SMEM_BYTES (WR_OFF_B + 16 * WRING_B)         // 212992

__device__ int g_chunk_b0[MAXC];
__device__ int g_chunk_b1[MAXC];
__device__ int g_chunk_e [MAXC];
__device__ int g_nchunks;

__global__ void pmst_prepass(const int* __restrict__ emb_ids) {
    const int e = threadIdx.x;             // 0..31
    int cnt = 0;
    for (int b = 0; b < BB; b++) cnt += (emb_ids[b] == e);
    int pairs = (cnt + 1) >> 1;
    int off = pairs;
    #pragma unroll
    for (int d = 1; d < 32; d <<= 1) {
        int v = __shfl_up_sync(0xFFFFFFFFu, off, d);
        if (e >= d) off += v;
    }
    if (e == 31) g_nchunks = off;
    int idx = off - pairs;
    int prev = -1;
    for (int b = 0; b < BB; b++) {
        if (emb_ids[b] == e) {
            if (prev < 0) prev = b;
            else { g_chunk_b0[idx] = prev; g_chunk_b1[idx] = b; g_chunk_e[idx] = e; idx++; prev = -1; }
        }
    }
    if (prev >= 0) { g_chunk_b0[idx] = prev; g_chunk_b1[idx] = prev; g_chunk_e[idx] = e; }
}

__device__ __forceinline__ uint32_t f2tf(float f) {
    uint32_t r; asm("cvt.rna.tf32.f32 %0, %1;" : "=r"(r) : "f"(f)); return r;
}

// a0..a3 in mma fragment order
__device__ __forceinline__ void mma8(float* d, uint32_t a0, uint32_t a1, uint32_t a2, uint32_t a3,
                                     uint32_t b0, uint32_t b1) {
    asm volatile(
        "mma.sync.aligned.m16n8k8.row.col.f32.tf32.tf32.f32 "
        "{%0,%1,%2,%3}, {%4,%5,%6,%7}, {%8,%9}, {%0,%1,%2,%3};"
        : "+f"(d[0]), "+f"(d[1]), "+f"(d[2]), "+f"(d[3])
        : "r"(a0), "r"(a1), "r"(a2), "r"(a3), "r"(b0), "r"(b1));
}

#define CP_COMMIT() asm volatile("cp.async.commit_group;" ::: "memory")
#define CP_WAIT2()  asm volatile("cp.async.wait_group 2;" ::: "memory")
#define CP_WAIT0()  asm volatile("cp.async.wait_group 0;" ::: "memory")

// Each lane copies exactly the 2x16B it will read back: rows (tg, tg+4), cols 4g..4g+3.
__device__ __forceinline__ void issue_wslab(uint32_t stage, const float* __restrict__ wrow,
                                            int g, int tg) {
    const float* sA = wrow + (long)tg * 512 + 4 * g;
    const float* sB = sA + 4 * 512;
    const uint32_t dA = stage + (uint32_t)(tg * WROW_B + g * 16);
    const uint32_t dB = dA + 4 * WROW_B;
    asm volatile("cp.async.cg.shared.global [%0], [%1], 16;" :: "r"(dA), "l"(sA) : "memory");
    asm volatile("cp.async.cg.shared.global [%0], [%1], 16;" :: "r"(dB), "l"(sB) : "memory");
}

__device__ __forceinline__ void lds128(float4& v, uint32_t addr) {
    asm volatile("ld.shared.v4.f32 {%0,%1,%2,%3}, [%4];"
                 : "=f"(v.x), "=f"(v.y), "=f"(v.z), "=f"(v.w) : "r"(addr));
}

// pair-interleave within 8-col group: original col j (0..7) stored at 2*(j&3) + (j>>2)
__device__ __forceinline__ int sigma8(int k) { return (k & ~7) + 2 * (k & 3) + ((k >> 2) & 1); }

// grid = (MAXC, MM); block = 512 threads (16 warps). Warp tile: 64 rows x 32 cols.
// Column perm (gmem side): logical mma col (8*nt + j) == physical col (ncol0 + 4*j + nt).
// A-side perm (smem side): sigma8 pair-interleave -> LDS.64 fragments.
__global__ __launch_bounds__(512, 1) void pmst_mma_kernel(
    const float* __restrict__ state,   // [B, T, M*DIN]
    const float* __restrict__ W1,      // [M, NEMB, DIN, H]
    const float* __restrict__ b1,      // [M, NEMB, H]
    const float* __restrict__ W2,      // [M, NEMB, H, E]
    const float* __restrict__ b2,      // [M, NEMB, E]
    const float* __restrict__ te,      // [M, E]
    float* __restrict__ out)           // [B, M*T, E]
{
    const int c = blockIdx.x;
    if (c >= g_nchunks) return;
    const int m   = blockIdx.y;
    const int e   = g_chunk_e[c];
    const int b0  = g_chunk_b0[c];
    const int b1v = g_chunk_b1[c];

    extern __shared__ uint32_t smu[];
    uint32_t* Xs = smu;                        // [ROWS][XS_STRIDE] sigma8-permuted
    uint32_t* Hs = smu + ROWS * XS_STRIDE;     // [ROWS][HS_STRIDE] sigma8-permuted
    uint32_t smem_base;
    asm("{ .reg .u64 t; cvta.to.shared.u64 t, %1; cvt.u32.u64 %0, t; }"
        : "=r"(smem_base) : "l"((const void*)smu));

    const int tid  = threadIdx.x;
    const int wid  = tid >> 5;
    const int lane = tid & 31;
    const int g    = lane >> 2;    // 0..7
    const int tg   = lane & 3;     // 0..3

    const uint32_t wring = smem_base + WR_OFF_B + wid * WRING_B;
    const uint32_t wfrag = (uint32_t)(tg * WROW_B + g * 16);

    const long me = (long)m * NEMB + e;
    const float* W1p = W1 + me * (DINN * HHH);
    const float* W2p = W2 + me * ((long)HHH * EEE);
    const float* b1p = b1 + me * HHH;
    const float* b2p = b2 + me * EEE;
    const float* tep = te + (long)m * EEE;

    const int ncol0 = wid * 32;
    const float* w1base = W1p + ncol0;
    const float* w2base = W2p + ncol0;
    float acc[4][4][4];   // [m-tile][n-tile][frag]

    // ---- GEMM1 prologue: stages 0,1 in flight ----
    issue_wslab(wring + 0 * WSTG_B, w1base,           g, tg); CP_COMMIT();
    issue_wslab(wring + 1 * WSTG_B, w1base + 8 * HHH, g, tg); CP_COMMIT();

    // ---- Stage X (sigma8-permuted, tf32) ----
    #pragma unroll
    for (int i = tid; i < ROWS * DINN; i += 512) {
        const int tr = i >> 6, k = i & 63;
        const int bb = (tr < TT) ? b0 : b1v;
        const int t  = tr & (TT - 1);
        Xs[tr * XS_STRIDE + sigma8(k)] =
            f2tf(__ldg(state + ((long)bb * TT + t) * (MM * DINN) + m * DINN + k));
    }
    __syncthreads();

    // ================= GEMM1: H = relu(X @ W1 + b1) =================
    #pragma unroll
    for (int mt = 0; mt < 4; mt++)
        #pragma unroll
        for (int nt = 0; nt < 4; nt++)
            #pragma unroll
            for (int i = 0; i < 4; i++) acc[mt][nt][i] = 0.f;
    {
        int stg = 0;
        #pragma unroll
        for (int kc = 0; kc < 8; kc++) {
            // A fragments first (LDS.64 pairs), overlap with cp wait
            uint2 u0[4], u1[4];
            {
                const uint32_t* xb = Xs + g * XS_STRIDE + 2 * tg + kc * 8;
                #pragma unroll
                for (int mt = 0; mt < 4; mt++) {
                    u0[mt] = *(const uint2*)(xb + mt * 16 * XS_STRIDE);
                    u1[mt] = *(const uint2*)(xb + (mt * 16 + 8) * XS_STRIDE);
                }
            }
            if (kc + 2 < 8) issue_wslab(wring + ((stg + 2) % 3) * WSTG_B,
                                        w1base + (long)(kc + 2) * 8 * HHH, g, tg);
            CP_COMMIT();
            CP_WAIT2();

            float4 v0, v1;
            const uint32_t baseA = wring + stg * WSTG_B + wfrag;
            lds128(v0, baseA);
            lds128(v1, baseA + 4 * WROW_B);
            const uint32_t w0[4]  = { f2tf(v0.x), f2tf(v0.y), f2tf(v0.z), f2tf(v0.w) };
            const uint32_t w1f[4] = { f2tf(v1.x), f2tf(v1.y), f2tf(v1.z), f2tf(v1.w) };
            #pragma unroll
            for (int nt = 0; nt < 4; nt++)
                #pragma unroll
                for (int mt = 0; mt < 4; mt++)
                    mma8(acc[mt][nt], u0[mt].x, u1[mt].x, u0[mt].y, u1[mt].y, w0[nt], w1f[nt]);
            if (++stg == 3) stg = 0;
        }
    }

    // ---- GEMM2 prologue (overlaps epilogue1 + barrier) ----
    CP_WAIT0();
    issue_wslab(wring + 0 * WSTG_B, w2base,           g, tg); CP_COMMIT();
    issue_wslab(wring + 1 * WSTG_B, w2base + 8 * EEE, g, tg); CP_COMMIT();

    // ---- epilogue1: relu + bias -> Hs (physical col group pc..pc+7, sigma8 order) ----
    {
        const int pc = ncol0 + 8 * tg;        // this thread's full 8-col group
        const float4 bL = __ldg((const float4*)(b1p + pc));
        const float4 bH = __ldg((const float4*)(b1p + pc + 4));
        #pragma unroll
        for (int mt = 0; mt < 4; mt++) {
            const int r0 = mt * 16 + g;
            const int r1 = r0 + 8;
            // word order in group: (c0,c4,c1,c5 | c2,c6,c3,c7); c_nt=frag f, c_{4+nt}=frag f+1
            uint4 wA, wB;
            wA.x = f2tf(fmaxf(acc[mt][0][0] + bL.x, 0.f));
            wA.y = f2tf(fmaxf(acc[mt][0][1] + bH.x, 0.f));
            wA.z = f2tf(fmaxf(acc[mt][1][0] + bL.y, 0.f));
            wA.w = f2tf(fmaxf(acc[mt][1][1] + bH.y, 0.f));
            wB.x = f2tf(fmaxf(acc[mt][2][0] + bL.z, 0.f));
            wB.y = f2tf(fmaxf(acc[mt][2][1] + bH.z, 0.f));
            wB.z = f2tf(fmaxf(acc[mt][3][0] + bL.w, 0.f));
            wB.w = f2tf(fmaxf(acc[mt][3][1] + bH.w, 0.f));
            *(uint4*)(Hs + r0 * HS_STRIDE + pc)     = wA;
            *(uint4*)(Hs + r0 * HS_STRIDE + pc + 4) = wB;
            wA.x = f2tf(fmaxf(acc[mt][0][2] + bL.x, 0.f));
            wA.y = f2tf(fmaxf(acc[mt][0][3] + bH.x, 0.f));
            wA.z = f2tf(fmaxf(acc[mt][1][2] + bL.y, 0.f));
            wA.w = f2tf(fmaxf(acc[mt][1][3] + bH.y, 0.f));
            wB.x = f2tf(fmaxf(acc[mt][2][2] + bL.z, 0.f));
            wB.y = f2tf(fmaxf(acc[mt][2][3] + bH.z, 0.f));
            wB.z = f2tf(fmaxf(acc[mt][3][2] + bL.w, 0.f));
            wB.w = f2tf(fmaxf(acc[mt][3][3] + bH.w, 0.f));
            *(uint4*)(Hs + r1 * HS_STRIDE + pc)     = wA;
            *(uint4*)(Hs + r1 * HS_STRIDE + pc + 4) = wB;
        }
    }
    __syncthreads();

    // ================= GEMM2: Z = H @ W2 + b2 + te =================
    #pragma unroll
    for (int mt = 0; mt < 4; mt++)
        #pragma unroll
        for (int nt = 0; nt < 4; nt++)
            #pragma unroll
            for (int i = 0; i < 4; i++) acc[mt][nt][i] = 0.f;
    {
        int stg = 0;
        #pragma unroll 4
        for (int kc = 0; kc < 64; kc++) {
            uint2 u0[4], u1[4];
            {
                const uint32_t* hb = Hs + g * HS_STRIDE + 2 * tg + kc * 8;
                #pragma unroll
                for (int mt = 0; mt < 4; mt++) {
                    u0[mt] = *(const uint2*)(hb + mt * 16 * HS_STRIDE);
                    u1[mt] = *(const uint2*)(hb + (mt * 16 + 8) * HS_STRIDE);
                }
            }
            if (kc + 2 < 64) issue_wslab(wring + ((stg + 2) % 3) * WSTG_B,
                                         w2base + (long)(kc + 2) * 8 * EEE, g, tg);
            CP_COMMIT();
            CP_WAIT2();

            float4 v0, v1;
            const uint32_t baseA = wring + stg * WSTG_B + wfrag;
            lds128(v0, baseA);
            lds128(v1, baseA + 4 * WROW_B);
            const uint32_t w0[4]  = { f2tf(v0.x), f2tf(v0.y), f2tf(v0.z), f2tf(v0.w) };
            const uint32_t w1f[4] = { f2tf(v1.x), f2tf(v1.y), f2tf(v1.z), f2tf(v1.w) };
            #pragma unroll
            for (int nt = 0; nt < 4; nt++)
                #pragma unroll
                for (int mt = 0; mt < 4; mt++)
                    mma8(acc[mt][nt], u0[mt].x, u1[mt].x, u0[mt].y, u1[mt].y, w0[nt], w1f[nt]);
            if (++stg == 3) stg = 0;
        }
    }

    // ---- epilogue2: out[b, m*T + t, physical col] (unchanged mapping) ----
    {
        const int pc = ncol0 + 8 * tg;
        const float4 bL = __ldg((const float4*)(b2p + pc));
        const float4 bH = __ldg((const float4*)(b2p + pc + 4));
        const float4 tL = __ldg((const float4*)(tep + pc));
        const float4 tH = __ldg((const float4*)(tep + pc + 4));
        const float4 aL = make_float4(bL.x + tL.x, bL.y + tL.y, bL.z + tL.z, bL.w + tL.w);
        const float4 aH = make_float4(bH.x + tH.x, bH.y + tH.y, bH.z + tH.z, bH.w + tH.w);
        float* op0 = out + ((long)b0  * MM + m) * TT * EEE;
        float* op1 = out + ((long)b1v * MM + m) * TT * EEE;
        #pragma unroll
        for (int mt = 0; mt < 4; mt++) {
            const int r0 = mt * 16 + g;
            const int r1 = r0 + 8;
            float* p0 = ((r0 < TT) ? op0 : op1) + (long)(r0 & (TT - 1)) * EEE + pc;
            float* p1 = ((r1 < TT) ? op0 : op1) + (long)(r1 & (TT - 1)) * EEE + pc;
            *(float4*)p0 = make_float4(acc[mt][0][0] + aL.x, acc[mt][1][0] + aL.y,
                                       acc[mt][2][0] + aL.z, acc[mt][3][0] + aL.w);
            *(float4*)(p0 + 4) = make_float4(acc[mt][0][1] + aH.x, acc[mt][1][1] + aH.y,
                                             acc[mt][2][1] + aH.z, acc[mt][3][1] + aH.w);
            *(float4*)p1 = make_float4(acc[mt][0][2] + aL.x, acc[mt][1][2] + aL.y,
                                       acc[mt][2][2] + aL.z, acc[mt][3][2] + aL.w);
            *(float4*)(p1 + 4) = make_float4(acc[mt][0][3] + aH.x, acc[mt][1][3] + aH.y,
                                             acc[mt][2][3] + aH.z, acc[mt][3][3] + aH.w);
        }
    }
}

extern "C" void kernel_launch(void* const* d_in, const int* in_sizes, int n_in,
                              void* d_out, int out_size)
{
    const float* state   = (const float*)d_in[0];
    const int*   emb_ids = (const int*)  d_in[1];
    const float* W1      = (const float*)d_in[2];
    const float* b1      = (const float*)d_in[3];
    const float* W2      = (const float*)d_in[4];
    const float* b2      = (const float*)d_in[5];
    const float* te      = (const float*)d_in[6];
    float*       out     = (float*)d_out;

    pmst_prepass<<<1, 32>>>(emb_ids);

    cudaFuncSetAttribute(pmst_mma_kernel,
                         cudaFuncAttributeMaxDynamicSharedMemorySize, SMEM_BYTES);

    dim3 grid(MAXC, MM);
    pmst_mma_kernel<<<grid, 512, SMEM_BYTES>>>(state, W1, b1, W2, b2, te, out);
}